// round 7
// baseline (speedup 1.0000x reference)
#include <cuda_runtime.h>
typedef unsigned long long ull;

// k-pair counts per layer (K = 129, 257, 385)
#define KP1 65
#define KP2 129
#define KP3 193
#define WO_2 (KP1*128)              // 8320
#define WO_3 ((KP1+KP2)*128)        // 24832
#define WTOT ((KP1+KP2+KP3)*128)    // 49536
#define OFF_A  WTOT                 // A2: 193*32 = 6176 floats
#define OFF_G  (OFF_A + 6176)       // G: 64*16
#define OFF_BS (OFF_G + 1024)       // 3*64
#define OFF_WL (OFF_BS + 192)       // 386
#define SMEM_FLOATS (OFF_WL + 386)  // 57314
#define SMEM_BYTES  (SMEM_FLOATS*4) // 229256 B

__device__ __forceinline__ void cluster_sync_() {
    asm volatile("barrier.cluster.arrive.aligned;" ::: "memory");
    asm volatile("barrier.cluster.wait.aligned;" ::: "memory");
}
__device__ __forceinline__ void fma2(ull& a, ull b, ull c) {
    asm("fma.rn.f32x2 %0, %1, %2, %0;" : "+l"(a) : "l"(b), "l"(c));
}
__device__ __forceinline__ ull addb16(ull v) {
    ull o = __shfl_xor_sync(0xffffffffu, v, 16);
    ull r; asm("add.rn.f32x2 %0, %1, %2;" : "=l"(r) : "l"(v), "l"(o));
    return r;
}
__device__ __forceinline__ float hadd(ull v) {
    float lo, hi; asm("mov.b64 {%0,%1}, %2;" : "=f"(lo), "=f"(hi) : "l"(v));
    return lo + hi;
}
__device__ __forceinline__ float tha(float x) {
    float y; asm("tanh.approx.f32 %0, %1;" : "=f"(y) : "f"(x)); return y;
}
__device__ __forceinline__ void stcr(unsigned ra, float v) {
    asm volatile("st.shared::cluster.f32 [%0], %1;" :: "r"(ra), "f"(v) : "memory");
}

__global__ void __launch_bounds__(512, 1) __cluster_dims__(8, 1, 1)
lstm_k(const float* __restrict__ x,
       const float* __restrict__ Wih1, const float* __restrict__ Whh1,
       const float* __restrict__ bih1, const float* __restrict__ bhh1,
       const float* __restrict__ Wih2, const float* __restrict__ Whh2,
       const float* __restrict__ bih2, const float* __restrict__ bhh2,
       const float* __restrict__ Wih3, const float* __restrict__ Whh3,
       const float* __restrict__ bih3, const float* __restrict__ bhh3,
       const float* __restrict__ Wlin, const float* __restrict__ blin,
       float* __restrict__ out)
{
    extern __shared__ float sm[];
    float* W2 = sm;
    float* A2 = sm + OFF_A;
    float* G  = sm + OFF_G;
    float* BS = sm + OFF_BS;
    float* WL = sm + OFF_WL;

    const int tid = threadIdx.x;
    unsigned rank; asm("mov.u32 %0, %%cluster_ctarank;" : "=r"(rank));
    const int b0 = (blockIdx.x >> 3) * 16;

    // ---- one-time weight load: interleaved k-pairs, i/f/o rows pre-scaled 0.5 ----
    {
        const float* WihA[3] = {Wih1, Wih2, Wih3};
        const float* WhhA[3] = {Whh1, Whh2, Whh3};
        const float* bihA[3] = {bih1, bih2, bih3};
        const float* bhhA[3] = {bhh1, bhh2, bhh3};
        const int KihA[3] = {1, 129, 257};
        const int KA[3]   = {129, 257, 385};
        const int KPA[3]  = {KP1, KP2, KP3};
        const int WOA[3]  = {0, WO_2, WO_3};
        for (int L = 0; L < 3; L++) {
            const int K = KA[L], Kih = KihA[L], KP = KPA[L];
            float* Wd = W2 + WOA[L];
            for (int i = tid; i < KP*128; i += 512) {
                int kp = i >> 7, r = i & 127;
                int l = r >> 1, par = r & 1, k = 2*kp + par;
                float v = 0.0f;
                if (k < K) {
                    int grow = ((l >> 4) << 7) + ((int)rank << 4) + (l & 15);
                    v = (k < Kih) ? WihA[L][grow*Kih + k]
                                  : WhhA[L][grow*128 + (k - Kih)];
                    if ((l >> 4) != 2) v *= 0.5f;     // i,f,o rows scaled for tanh-sigmoid
                }
                Wd[i] = v;
            }
            if (tid < 64) {
                int grow = ((tid >> 4) << 7) + ((int)rank << 4) + (tid & 15);
                float b = bihA[L][grow] + bhhA[L][grow];
                if ((tid >> 4) != 2) b *= 0.5f;
                BS[L*64 + tid] = b;
            }
        }
        for (int i = tid; i < 385; i += 512) WL[i] = Wlin[i];
        if (tid == 0) WL[385] = blin[0];
        for (int i = tid; i < 6176; i += 512) A2[i] = 0.0f;
    }
    __syncthreads();

    // remote A2 base addresses for all 8 cluster ranks
    const unsigned abase = (unsigned)__cvta_generic_to_shared(A2);
    unsigned rb[8];
    #pragma unroll
    for (int r = 0; r < 8; r++) {
        unsigned ra;
        asm("mapa.shared::cluster.u32 %0, %1, %2;" : "=r"(ra) : "r"(abase), "r"((unsigned)r));
        rb[r] = ra;
    }

    const int warpid = tid >> 5, lane = tid & 31;
    const int lgrp = warpid & 3, bq = warpid >> 2;
    const int l  = (lgrp << 4) + (lane & 15);   // gate row 0..63
    const int kh = lane >> 4;                   // k-half within warp
    const int ej = tid >> 3, ebp = tid & 7;     // epilogue: row j, batch pair
    float cst[3][2] = {{0.f,0.f},{0.f,0.f},{0.f,0.f}};
    float xn = (tid < 16) ? x[(b0 + tid) * 1024] : 0.0f;

    for (int t = 0; t < 1056; t++) {
        if (t < 1024 && tid < 16) A2[2*tid] = xn;   // x slot: g=0 -> pos 2b
        __syncthreads();
        if (tid < 16 && t + 1 < 1024) xn = x[(b0 + tid)*1024 + t + 1];

        #pragma unroll
        for (int L = 0; L < 3; L++) {
            const int KP = (L==0) ? KP1 : (L==1) ? KP2 : KP3;
            const int I  = (KP + 1) >> 1;
            const float* Wd = W2 + ((L==0) ? 0 : (L==1) ? WO_2 : WO_3);

            ull a0=0, a1=0, a2=0, a3=0;
            int kp = kh * I;
            const int kend = kh ? KP : I;
            #pragma unroll 4
            for (; kp < kend; kp++) {
                const int sw = (kp & 1) << 4;
                ull w2 = *(const ull*)(Wd + (kp << 7) + (l << 1));
                const float* ap = A2 + (kp << 5) + ((bq << 3) ^ sw);
                ulonglong2 q0 = *(const ulonglong2*)(ap);
                ulonglong2 q1 = *(const ulonglong2*)(ap + 4);
                fma2(a0, w2, q0.x); fma2(a1, w2, q0.y);
                fma2(a2, w2, q1.x); fma2(a3, w2, q1.y);
            }
            a0 = addb16(a0); a1 = addb16(a1); a2 = addb16(a2); a3 = addb16(a3);
            if (kh == 0)
                *(float4*)(G + l*16 + (bq << 2)) =
                    make_float4(hadd(a0), hadd(a1), hadd(a2), hadd(a3));
            __syncthreads();

            // epilogue: 128 threads, 2 cells each (pre-scaled tanh-form gates)
            float hva = 0.f, hvb = 0.f;
            if (tid < 128) {
                const int j = ej, ba = 2*ebp;
                const float bi = BS[L*64 + j],      bf = BS[L*64 + 16 + j];
                const float bg = BS[L*64 + 32 + j], bo = BS[L*64 + 48 + j];
                {
                    float ii = fmaf(0.5f, tha(G[j*16 + ba] + bi), 0.5f);
                    float ff = fmaf(0.5f, tha(G[(16+j)*16 + ba] + bf), 0.5f);
                    float gg = tha(G[(32+j)*16 + ba] + bg);
                    float oo = fmaf(0.5f, tha(G[(48+j)*16 + ba] + bo), 0.5f);
                    float c = ff * cst[L][0] + ii * gg;
                    cst[L][0] = c;
                    hva = oo * tha(c);
                }
                {
                    float ii = fmaf(0.5f, tha(G[j*16 + ba+1] + bi), 0.5f);
                    float ff = fmaf(0.5f, tha(G[(16+j)*16 + ba+1] + bf), 0.5f);
                    float gg = tha(G[(32+j)*16 + ba+1] + bg);
                    float oo = fmaf(0.5f, tha(G[(48+j)*16 + ba+1] + bo), 0.5f);
                    float c = ff * cst[L][1] + ii * gg;
                    cst[L][1] = c;
                    hvb = oo * tha(c);
                }
            }
            cluster_sync_();   // all ranks' matvec reads of A2 complete

            if (tid < 128) {   // broadcast h to every rank's A2
                const int g = 1 + (L << 7) + ((int)rank << 4) + ej;
                const int kp2 = g >> 1, par = g & 1, sw = (kp2 & 1) << 4;
                const unsigned offA = (unsigned)((kp2 << 5) + ((4*ebp + par) ^ sw)) << 2;
                const unsigned offB = (unsigned)((kp2 << 5) + ((4*ebp + 2 + par) ^ sw)) << 2;
                #pragma unroll
                for (int r = 0; r < 8; r++) { stcr(rb[r] + offA, hva); stcr(rb[r] + offB, hvb); }
            }
            cluster_sync_();   // h visible everywhere
        }

        // distributed linear head: this CTA handles batches 2*rank, 2*rank+1
        if (tid < 64) {
            const int w = tid >> 5, ln = tid & 31;
            const int b = 2*(int)rank + w;
            float s = 0.f;
            for (int g = ln; g < 385; g += 32) {
                const int kp = g >> 1;
                const int pos = (2*b + (g & 1)) ^ ((kp & 1) << 4);
                s += A2[(kp << 5) + pos] * WL[g];
            }
            #pragma unroll
            for (int off = 16; off; off >>= 1) s += __shfl_xor_sync(0xffffffffu, s, off);
            if (ln == 0) {
                const float o = s + WL[385];
                out[(b0 + b)*1056 + t] = o;
                if (t >= 1023) {                 // autoregressive feedback -> x slot
                    const unsigned offx = (unsigned)(2*b) << 2;
                    #pragma unroll
                    for (int r = 0; r < 8; r++) stcr(rb[r] + offx, o);
                }
            }
        }
        cluster_sync_();       // feedback/out done before next step writes A2
    }
}

extern "C" void kernel_launch(void* const* d_in, const int* in_sizes, int n_in,
                              void* d_out, int out_size) {
    cudaFuncSetAttribute(lstm_k, cudaFuncAttributeMaxDynamicSharedMemorySize, SMEM_BYTES);
    lstm_k<<<128, 512, SMEM_BYTES>>>(
        (const float*)d_in[0],
        (const float*)d_in[1], (const float*)d_in[2],
        (const float*)d_in[3], (const float*)d_in[4],
        (const float*)d_in[5], (const float*)d_in[6],
        (const float*)d_in[7], (const float*)d_in[8],
        (const float*)d_in[9], (const float*)d_in[10],
        (const float*)d_in[11], (const float*)d_in[12],
        (const float*)d_in[13], (const float*)d_in[14],
        (float*)d_out);
}

// round 9
// speedup vs baseline: 1.2448x; 1.2448x over previous
#include <cuda_runtime.h>
typedef unsigned long long ull;

#define WO1 0
#define WO2 (65*128)
#define WO3 (194*128)
#define WTOT (387*128)            // 49536 floats
#define OFF_A  WTOT               // A2: 193 kp * 32 = 6176
#define OFF_G  (OFF_A + 6176)     // 64*16
#define OFF_BS (OFF_G + 1024)     // 3*64
#define OFF_WL (OFF_BS + 192)     // 386 (+2 pad)
#define OFF_MB (OFF_WL + 388)     // 8 mbarriers (8B aligned)
#define SMEM_FLOATS (OFF_MB + 16)
#define SMEM_BYTES (SMEM_FLOATS*4)

__device__ __forceinline__ void fma2(ull& a, ull b, ull c) {
    asm("fma.rn.f32x2 %0, %1, %2, %0;" : "+l"(a) : "l"(b), "l"(c));
}
__device__ __forceinline__ ull addb16(ull v) {
    ull o = __shfl_xor_sync(0xffffffffu, v, 16);
    ull r; asm("add.rn.f32x2 %0, %1, %2;" : "=l"(r) : "l"(v), "l"(o));
    return r;
}
__device__ __forceinline__ float hadd(ull v) {
    float lo, hi; asm("mov.b64 {%0,%1}, %2;" : "=f"(lo), "=f"(hi) : "l"(v));
    return lo + hi;
}
__device__ __forceinline__ float tha(float x) {
    float y; asm("tanh.approx.f32 %0, %1;" : "=f"(y) : "f"(x)); return y;
}
__device__ __forceinline__ unsigned mapa_(unsigned a, int r) {
    unsigned ra; asm("mapa.shared::cluster.u32 %0, %1, %2;" : "=r"(ra) : "r"(a), "r"(r));
    return ra;
}
__device__ __forceinline__ void mbinit(unsigned a, unsigned n) {
    asm volatile("mbarrier.init.shared.b64 [%0], %1;" :: "r"(a), "r"(n) : "memory");
}
__device__ __forceinline__ void exptx(unsigned a, unsigned n) {
    asm volatile("mbarrier.arrive.expect_tx.shared.b64 _, [%0], %1;" :: "r"(a), "r"(n) : "memory");
}
__device__ __forceinline__ void rarr(unsigned a, int r) {
    unsigned ra = mapa_(a, r);
    asm volatile("mbarrier.arrive.release.cluster.shared::cluster.b64 _, [%0];" :: "r"(ra) : "memory");
}
__device__ __forceinline__ void sta(unsigned d, unsigned m, float v) {
    asm volatile("st.async.shared::cluster.mbarrier::complete_tx::bytes.b32 [%0], %1, [%2];"
                 :: "r"(d), "r"(__float_as_uint(v)), "r"(m) : "memory");
}
__device__ __forceinline__ void waitp(unsigned a, unsigned p) {
    unsigned d;
    asm volatile("{\n.reg .pred P;\nmbarrier.try_wait.parity.acquire.cluster.shared::cta.b64 P,[%1],%2;\nselp.b32 %0,1,0,P;\n}"
                 : "=r"(d) : "r"(a), "r"(p) : "memory");
    while (!d)
        asm volatile("{\n.reg .pred P;\nmbarrier.try_wait.parity.acquire.cluster.shared::cta.b64 P,[%1],%2,0x989680;\nselp.b32 %0,1,0,P;\n}"
                     : "=r"(d) : "r"(a), "r"(p) : "memory");
}
__device__ __forceinline__ void seg(const float* __restrict__ Wd, const float* __restrict__ Ab,
                                    int n, int kh, int l2, int bq8,
                                    ull& a0, ull& a1, ull& a2, ull& a3) {
    int s = kh ? (n >> 1) : 0;
    int e = kh ? n : (n >> 1);
    #pragma unroll 4
    for (int kp = s; kp < e; kp++) {
        ull w2 = *(const ull*)(Wd + (kp << 7) + l2);
        const ull* q = (const ull*)(Ab + (kp << 5) + bq8);
        fma2(a0, w2, q[0]); fma2(a1, w2, q[1]);
        fma2(a2, w2, q[2]); fma2(a3, w2, q[3]);
    }
}

__global__ void __launch_bounds__(512, 1) __cluster_dims__(8, 1, 1)
lstm_k(const float* __restrict__ xg,
       const float* __restrict__ Wih1, const float* __restrict__ Whh1,
       const float* __restrict__ bih1, const float* __restrict__ bhh1,
       const float* __restrict__ Wih2, const float* __restrict__ Whh2,
       const float* __restrict__ bih2, const float* __restrict__ bhh2,
       const float* __restrict__ Wih3, const float* __restrict__ Whh3,
       const float* __restrict__ bih3, const float* __restrict__ bhh3,
       const float* __restrict__ Wlin, const float* __restrict__ blin,
       float* __restrict__ out)
{
    extern __shared__ float sm[];
    float* W  = sm;
    float* A2 = sm + OFF_A;
    float* G  = sm + OFF_G;
    float* BS = sm + OFF_BS;
    float* WL = sm + OFF_WL;

    const int tid = threadIdx.x;
    unsigned ur; asm("mov.u32 %0, %%cluster_ctarank;" : "=r"(ur));
    const int rank = (int)ur;
    const int b0 = (blockIdx.x >> 3) * 16;

    const unsigned sbase = (unsigned)__cvta_generic_to_shared(sm);
    const unsigned e1 = sbase + (OFF_MB + 0)*4,  e2 = sbase + (OFF_MB + 2)*4;
    const unsigned e3 = sbase + (OFF_MB + 4)*4;
    const unsigned f1 = sbase + (OFF_MB + 6)*4,  f2 = sbase + (OFF_MB + 8)*4;
    const unsigned f3 = sbase + (OFF_MB + 10)*4;
    const unsigned fx = sbase + (OFF_MB + 12)*4, ex = sbase + (OFF_MB + 14)*4;

    // ---- one-time load: W interleaved k-pairs, col order [h_L rec | x,pad | h1 | h2] ----
    {
        const float* WihA[3] = {Wih1, Wih2, Wih3};
        const float* WhhA[3] = {Whh1, Whh2, Whh3};
        const float* bihA[3] = {bih1, bih2, bih3};
        const float* bhhA[3] = {bhh1, bhh2, bhh3};
        const int KihA[3] = {1, 129, 257};
        const int KPA[3]  = {65, 129, 193};
        const int WOA[3]  = {WO1, WO2, WO3};
        for (int L = 0; L < 3; L++) {
            const int Kih = KihA[L], KP = KPA[L];
            float* Wd = W + WOA[L];
            for (int i = tid; i < KP*128; i += 512) {
                int wkp = i >> 7, r = i & 127, l = r >> 1, par = r & 1;
                int grow = ((l >> 4) << 7) + (rank << 4) + (l & 15);
                float v;
                if (wkp < 64)        v = WhhA[L][grow*128 + 2*wkp + par];
                else if (wkp == 64)  v = par ? 0.0f : WihA[L][grow*Kih];
                else                 v = WihA[L][grow*Kih + 1 + 2*(wkp - 65) + par];
                if ((l >> 4) != 2) v *= 0.5f;   // i,f,o pre-scaled for tanh-sigmoid
                Wd[i] = v;
            }
            if (tid < 64) {
                int grow = ((tid >> 4) << 7) + (rank << 4) + (tid & 15);
                float b = bihA[L][grow] + bhhA[L][grow];
                if ((tid >> 4) != 2) b *= 0.5f;
                BS[L*64 + tid] = b;
            }
        }
        for (int i = tid; i < 384; i += 512) WL[i] = Wlin[i + 1];
        if (tid == 0) { WL[384] = Wlin[0]; WL[385] = blin[0]; }
        for (int i = tid; i < 6176; i += 512) A2[i] = 0.0f;
        if (tid == 0) {
            mbinit(e1, 8); mbinit(e2, 8); mbinit(e3, 8); mbinit(ex, 8);
            mbinit(f1, 1); mbinit(f2, 1); mbinit(f3, 1); mbinit(fx, 1);
        }
    }
    __syncthreads();
    asm volatile("barrier.cluster.arrive.aligned;" ::: "memory");
    asm volatile("barrier.cluster.wait.aligned;" ::: "memory");

    const unsigned abase = sbase + OFF_A*4;
    unsigned rb[8];
    #pragma unroll
    for (int r = 0; r < 8; r++) rb[r] = mapa_(abase, r);

    const int warpid = tid >> 5, lane = tid & 31;
    const int l2  = (((warpid & 3) << 4) + (lane & 15)) << 1;
    const int kh  = lane >> 4;
    const int bq8 = (warpid >> 2) << 3;
    const int ej = tid >> 3, ebp = tid & 7;
    const int gr = ((warpid & 3) << 4) + (lane & 15);
    float cst[3][2] = {{0.f,0.f},{0.f,0.f},{0.f,0.f}};
    float xn = (tid < 16) ? xg[(b0 + tid) * 1024] : 0.0f;
    unsigned phx = 0;

    for (int t = 0; t < 1056; t++) {
        const unsigned pc = t & 1, pp = (t - 1) & 1;
        if (t < 1024 && tid < 16) A2[6144 + 2*tid] = xn;
        __syncthreads();
        if (tid < 16 && t + 1 < 1024) xn = xg[(b0 + tid)*1024 + t + 1];
        if (t >= 1024) { waitp(fx, phx); phx ^= 1; }
        // exptx AFTER consuming previous phase: barrier provably fresh now.
        if (tid == 0 && t >= 1023 && t < 1055) exptx(fx, 64);

        float hA = 0.f, hB = 0.f;
        #pragma unroll 1
        for (int L = 0; L < 3; L++) {
            const unsigned eL = (L==0) ? e1 : (L==1) ? e2 : e3;
            const unsigned fL = (L==0) ? f1 : (L==1) ? f2 : f3;
            const float* Wd = W + ((L==0) ? WO1 : (L==1) ? WO2 : WO3);
            if (t) waitp(fL, pp);              // recurrent h_L(t-1) arrived
            if (tid == 0) exptx(fL, 8192);     // fresh phase: post for h_L(t)
            ull a0=0, a1=0, a2=0, a3=0;
            seg(Wd, A2 + (L << 11), 64, kh, l2, bq8, a0, a1, a2, a3);   // rec h_L
            seg(Wd + 8192, A2 + 6144, 1, kh, l2, bq8, a0, a1, a2, a3);  // x
            __syncthreads();                   // early reads done CTA-wide (orders exptx too)
            if (tid < 8) rarr(eL, tid);        // read-done -> all ranks
            if (L >= 1) {
                waitp(f1, pc);
                seg(Wd + 8320, A2, 64, kh, l2, bq8, a0, a1, a2, a3);
            }
            if (L == 2) {
                waitp(f2, pc);
                seg(Wd + 16512, A2 + 2048, 64, kh, l2, bq8, a0, a1, a2, a3);
            }
            a0 = addb16(a0); a1 = addb16(a1); a2 = addb16(a2); a3 = addb16(a3);
            if (kh == 0)
                *(float4*)(G + gr*16 + (bq8 >> 1)) =
                    make_float4(hadd(a0), hadd(a1), hadd(a2), hadd(a3));
            __syncthreads();                   // G visible

            if (tid < 128) {                   // epilogue: 2 cells/thread
                const int ba = 2*ebp;
                const float bi = BS[L*64 + ej],      bf = BS[L*64 + 16 + ej];
                const float bg = BS[L*64 + 32 + ej], bo = BS[L*64 + 48 + ej];
                float ii = fmaf(0.5f, tha(G[ej*16 + ba] + bi), 0.5f);
                float ff = fmaf(0.5f, tha(G[(16+ej)*16 + ba] + bf), 0.5f);
                float gg = tha(G[(32+ej)*16 + ba] + bg);
                float oo = fmaf(0.5f, tha(G[(48+ej)*16 + ba] + bo), 0.5f);
                float c = ff*cst[L][0] + ii*gg; cst[L][0] = c; hA = oo*tha(c);
                ii = fmaf(0.5f, tha(G[ej*16 + ba+1] + bi), 0.5f);
                ff = fmaf(0.5f, tha(G[(16+ej)*16 + ba+1] + bf), 0.5f);
                gg = tha(G[(32+ej)*16 + ba+1] + bg);
                oo = fmaf(0.5f, tha(G[(48+ej)*16 + ba+1] + bo), 0.5f);
                c = ff*cst[L][1] + ii*gg; cst[L][1] = c; hB = oo*tha(c);
            }
            __syncthreads();                   // G reads done (next layer reuses G)
            if (tid < 128) {
                waitp(eL, pc);                 // all ranks freed the h_L slot
                const int s = L*128 + (rank << 4) + ej;
                const unsigned oa = (unsigned)(((s >> 1) << 5) + 4*ebp + (s & 1)) << 2;
                #pragma unroll
                for (int r = 0; r < 8; r++) {
                    unsigned rm = mapa_(fL, r);
                    sta(rb[r] + oa, rm, hA);
                    sta(rb[r] + oa + 8, rm, hB);
                }
            }
        }

        // head (needs h3(t) locally)
        float o = 0.f;
        const int hb = 2*rank + (tid >> 5);
        if (tid < 64) {
            waitp(f3, pc);
            float s = 0.f;
            for (int g = lane; g < 385; g += 32)
                s += A2[((g >> 1) << 5) + 2*hb + (g & 1)] * WL[g];
            #pragma unroll
            for (int off = 16; off; off >>= 1) s += __shfl_xor_sync(0xffffffffu, s, off);
            if (lane == 0) {
                o = s + WL[385];
                out[(b0 + hb)*1056 + t] = o;
            }
        }
        __syncthreads();                       // all x(t)/A2 reads done
        if (tid < 8) rarr(ex, tid);
        if (t >= 1023 && t < 1055 && tid < 64 && lane == 0) {
            waitp(ex, pc);                     // x slot free everywhere
            const unsigned ox = (unsigned)(6144 + 2*hb) << 2;
            #pragma unroll
            for (int r = 0; r < 8; r++) sta(rb[r] + ox, mapa_(fx, r), o);
        }
        __syncthreads();
    }

    if (tid == 0) { waitp(f1, 1); waitp(f2, 1); waitp(f3, 1); }
    __syncthreads();
    asm volatile("barrier.cluster.arrive.aligned;" ::: "memory");
    asm volatile("barrier.cluster.wait.aligned;" ::: "memory");
}

extern "C" void kernel_launch(void* const* d_in, const int* in_sizes, int n_in,
                              void* d_out, int out_size) {
    cudaFuncSetAttribute(lstm_k, cudaFuncAttributeMaxDynamicSharedMemorySize, SMEM_BYTES);
    lstm_k<<<128, 512, SMEM_BYTES>>>(
        (const float*)d_in[0],
        (const float*)d_in[1], (const float*)d_in[2],
        (const float*)d_in[3], (const float*)d_in[4],
        (const float*)d_in[5], (const float*)d_in[6],
        (const float*)d_in[7], (const float*)d_in[8],
        (const float*)d_in[9], (const float*)d_in[10],
        (const float*)d_in[11], (const float*)d_in[12],
        (const float*)d_in[13], (const float*)d_in[14],
        (float*)d_out);
}

// round 10
// speedup vs baseline: 1.3973x; 1.1224x over previous
#include <cuda_runtime.h>
typedef unsigned long long ull;

#define WO1 0
#define WO2 (65*128)
#define WO3 (194*128)
#define WTOT (387*128)            // 49536 floats
#define OFF_A  WTOT               // A2: 193 kp * 32 = 6176
#define OFF_G  (OFF_A + 6176)     // 64*16
#define OFF_WL (OFF_G + 1024)     // 386
#define OFF_MB (OFF_WL + 386)     // 57122 -> byte 228488 (8B aligned)
#define OFF_ST (OFF_MB + 18)      // 57140 -> byte 228560 (16B aligned)
#define SMEM_FLOATS (OFF_ST + 768)
#define SMEM_BYTES (SMEM_FLOATS*4)   // 231632 B

__device__ __forceinline__ void fma2(ull& a, ull b, ull c) {
    asm("fma.rn.f32x2 %0, %1, %2, %0;" : "+l"(a) : "l"(b), "l"(c));
}
__device__ __forceinline__ ull addb16(ull v) {
    ull o = __shfl_xor_sync(0xffffffffu, v, 16);
    ull r; asm("add.rn.f32x2 %0, %1, %2;" : "=l"(r) : "l"(v), "l"(o));
    return r;
}
__device__ __forceinline__ float hadd(ull v) {
    float lo, hi; asm("mov.b64 {%0,%1}, %2;" : "=f"(lo), "=f"(hi) : "l"(v));
    return lo + hi;
}
__device__ __forceinline__ float tha(float x) {
    float y; asm("tanh.approx.f32 %0, %1;" : "=f"(y) : "f"(x)); return y;
}
__device__ __forceinline__ unsigned mapa_(unsigned a, int r) {
    unsigned ra; asm("mapa.shared::cluster.u32 %0, %1, %2;" : "=r"(ra) : "r"(a), "r"(r));
    return ra;
}
__device__ __forceinline__ void mbinit(unsigned a, unsigned n) {
    asm volatile("mbarrier.init.shared.b64 [%0], %1;" :: "r"(a), "r"(n) : "memory");
}
__device__ __forceinline__ void exptx(unsigned a, unsigned n) {
    asm volatile("mbarrier.arrive.expect_tx.shared.b64 _, [%0], %1;" :: "r"(a), "r"(n) : "memory");
}
__device__ __forceinline__ void rarr(unsigned a, int r) {
    unsigned ra = mapa_(a, r);
    asm volatile("mbarrier.arrive.release.cluster.shared::cluster.b64 _, [%0];" :: "r"(ra) : "memory");
}
__device__ __forceinline__ void sta(unsigned d, unsigned m, float v) {
    asm volatile("st.async.shared::cluster.mbarrier::complete_tx::bytes.b32 [%0], %1, [%2];"
                 :: "r"(d), "r"(__float_as_uint(v)), "r"(m) : "memory");
}
__device__ __forceinline__ void blkcp(unsigned dst, unsigned src, unsigned mb) {
    asm volatile("cp.async.bulk.shared::cluster.shared::cta.mbarrier::complete_tx::bytes [%0], [%1], %2, [%3];"
                 :: "r"(dst), "r"(src), "r"(1024u), "r"(mb) : "memory");
}
__device__ __forceinline__ void waitp(unsigned a, unsigned p) {
    unsigned d;
    asm volatile("{\n.reg .pred P;\nmbarrier.try_wait.parity.acquire.cluster.shared::cta.b64 P,[%1],%2;\nselp.b32 %0,1,0,P;\n}"
                 : "=r"(d) : "r"(a), "r"(p) : "memory");
    while (!d)
        asm volatile("{\n.reg .pred P;\nmbarrier.try_wait.parity.acquire.cluster.shared::cta.b64 P,[%1],%2,0x989680;\nselp.b32 %0,1,0,P;\n}"
                     : "=r"(d) : "r"(a), "r"(p) : "memory");
}
__device__ __forceinline__ void seg(const float* __restrict__ Wd, const float* __restrict__ Ab,
                                    int n, int kh, int l2, int bq8,
                                    ull& a0, ull& a1, ull& a2, ull& a3) {
    int s = kh ? (n >> 1) : 0;
    int e = kh ? n : (n >> 1);
    #pragma unroll 4
    for (int kp = s; kp < e; kp++) {
        ull w2 = *(const ull*)(Wd + (kp << 7) + l2);
        const ull* q = (const ull*)(Ab + (kp << 5) + bq8);
        fma2(a0, w2, q[0]); fma2(a1, w2, q[1]);
        fma2(a2, w2, q[2]); fma2(a3, w2, q[3]);
    }
}

__global__ void __launch_bounds__(512, 1) __cluster_dims__(8, 1, 1)
lstm_k(const float* __restrict__ xg,
       const float* __restrict__ Wih1, const float* __restrict__ Whh1,
       const float* __restrict__ bih1, const float* __restrict__ bhh1,
       const float* __restrict__ Wih2, const float* __restrict__ Whh2,
       const float* __restrict__ bih2, const float* __restrict__ bhh2,
       const float* __restrict__ Wih3, const float* __restrict__ Whh3,
       const float* __restrict__ bih3, const float* __restrict__ bhh3,
       const float* __restrict__ Wlin, const float* __restrict__ blin,
       float* __restrict__ out)
{
    extern __shared__ float sm[];
    float* W  = sm;
    float* A2 = sm + OFF_A;
    float* G  = sm + OFF_G;
    float* WL = sm + OFF_WL;
    float* ST = sm + OFF_ST;

    const int tid = threadIdx.x;
    unsigned ur; asm("mov.u32 %0, %%cluster_ctarank;" : "=r"(ur));
    const int rank = (int)ur;
    const int b0 = (blockIdx.x >> 3) * 16;

    const unsigned sbase = (unsigned)__cvta_generic_to_shared(sm);
    const unsigned e1 = sbase + (OFF_MB + 0)*4,  e2 = sbase + (OFF_MB + 2)*4;
    const unsigned e3 = sbase + (OFF_MB + 4)*4;
    const unsigned f1 = sbase + (OFF_MB + 6)*4,  f2 = sbase + (OFF_MB + 8)*4;
    const unsigned f3 = sbase + (OFF_MB + 10)*4;
    const unsigned fx = sbase + (OFF_MB + 12)*4, ex = sbase + (OFF_MB + 14)*4;

    // ---- one-time load: W interleaved k-pairs, col order [h_L rec | x,pad | h1 | h2] ----
    {
        const float* WihA[3] = {Wih1, Wih2, Wih3};
        const float* WhhA[3] = {Whh1, Whh2, Whh3};
        const int KihA[3] = {1, 129, 257};
        const int KPA[3]  = {65, 129, 193};
        const int WOA[3]  = {WO1, WO2, WO3};
        for (int L = 0; L < 3; L++) {
            const int Kih = KihA[L], KP = KPA[L];
            float* Wd = W + WOA[L];
            for (int i = tid; i < KP*128; i += 512) {
                int wkp = i >> 7, r = i & 127, l = r >> 1, par = r & 1;
                int grow = ((l >> 4) << 7) + (rank << 4) + (l & 15);
                float v;
                if (wkp < 64)        v = WhhA[L][grow*128 + 2*wkp + par];
                else if (wkp == 64)  v = par ? 0.0f : WihA[L][grow*Kih];
                else                 v = WihA[L][grow*Kih + 1 + 2*(wkp - 65) + par];
                if ((l >> 4) != 2) v *= 0.5f;   // i,f,o pre-scaled for tanh-sigmoid
                Wd[i] = v;
            }
        }
        for (int i = tid; i < 384; i += 512) WL[i] = Wlin[i + 1];
        if (tid == 0) { WL[384] = Wlin[0]; WL[385] = blin[0]; }
        for (int i = tid; i < 6176; i += 512) A2[i] = 0.0f;
        if (tid == 0) {
            mbinit(e1, 8); mbinit(e2, 8); mbinit(e3, 8); mbinit(ex, 8);
            mbinit(f1, 1); mbinit(f2, 1); mbinit(f3, 1); mbinit(fx, 1);
        }
    }
    // per-thread epilogue biases in registers (pre-scaled)
    float bR[3][4];
    {
        const float* bihA[3] = {bih1, bih2, bih3};
        const float* bhhA[3] = {bhh1, bhh2, bhh3};
        #pragma unroll
        for (int L = 0; L < 3; L++)
            #pragma unroll
            for (int g = 0; g < 4; g++) {
                int grow = (g << 7) + (rank << 4) + ((tid >> 3) & 15);
                float b = bihA[L][grow] + bhhA[L][grow];
                bR[L][g] = (g == 2) ? b : 0.5f * b;
            }
    }
    __syncthreads();
    asm volatile("barrier.cluster.arrive.aligned;" ::: "memory");
    asm volatile("barrier.cluster.wait.aligned;" ::: "memory");

    const unsigned abase = sbase + OFF_A*4;
    unsigned rb[8];
    #pragma unroll
    for (int r = 0; r < 8; r++) rb[r] = mapa_(abase, r);

    const int warpid = tid >> 5, lane = tid & 31;
    const int l2  = (((warpid & 3) << 4) + (lane & 15)) << 1;
    const int kh  = lane >> 4;
    const int bq8 = (warpid >> 2) << 3;
    const int ej = tid >> 3, ebp = tid & 7;
    const int gr = ((warpid & 3) << 4) + (lane & 15);
    float cst[3][2] = {{0.f,0.f},{0.f,0.f},{0.f,0.f}};
    float xn = (tid < 16) ? xg[(b0 + tid) * 1024] : 0.0f;
    unsigned phx = 0;

#define LAYER(Lc, eL, fL, WOFF, PRE) do {                                     \
    const float* Wd = W + WOFF;                                               \
    if (t) waitp(fL, pp);                   /* recurrent h_L(t-1) arrived */  \
    if (tid == 0) exptx(fL, 8192);          /* fresh phase */                 \
    ull a0=0, a1=0, a2=0, a3=0;                                               \
    seg(Wd, A2 + (Lc << 11), 64, kh, l2, bq8, a0, a1, a2, a3);                \
    seg(Wd + 8192, A2 + 6144, 1, kh, l2, bq8, a0, a1, a2, a3);                \
    __syncthreads();                        /* early reads done CTA-wide */   \
    if (tid < 8) rarr(eL, tid);                                               \
    PRE                                                                       \
    a0 = addb16(a0); a1 = addb16(a1); a2 = addb16(a2); a3 = addb16(a3);       \
    if (kh == 0)                                                              \
        *(float4*)(G + gr*16 + (bq8 >> 1)) =                                  \
            make_float4(hadd(a0), hadd(a1), hadd(a2), hadd(a3));              \
    __syncthreads();                        /* G visible */                   \
    if (tid < 128) {                                                          \
        const int ba = 2*ebp;                                                 \
        const float bi = bR[Lc][0], bf = bR[Lc][1];                           \
        const float bg = bR[Lc][2], bo = bR[Lc][3];                           \
        float ii = fmaf(0.5f, tha(G[ej*16 + ba] + bi), 0.5f);                 \
        float ff = fmaf(0.5f, tha(G[(16+ej)*16 + ba] + bf), 0.5f);            \
        float gg = tha(G[(32+ej)*16 + ba] + bg);                              \
        float oo = fmaf(0.5f, tha(G[(48+ej)*16 + ba] + bo), 0.5f);            \
        float c = ff*cst[Lc][0] + ii*gg; cst[Lc][0] = c; float hA = oo*tha(c);\
        ii = fmaf(0.5f, tha(G[ej*16 + ba+1] + bi), 0.5f);                     \
        ff = fmaf(0.5f, tha(G[(16+ej)*16 + ba+1] + bf), 0.5f);                \
        gg = tha(G[(32+ej)*16 + ba+1] + bg);                                  \
        oo = fmaf(0.5f, tha(G[(48+ej)*16 + ba+1] + bo), 0.5f);                \
        c = ff*cst[Lc][1] + ii*gg; cst[Lc][1] = c; float hB = oo*tha(c);      \
        waitp(eL, pc);                      /* prev staging fully read */     \
        float* SL = ST + Lc*256;                                              \
        SL[(ej>>1)*32 + 4*ebp + (ej&1)] = hA;                                 \
        SL[(ej>>1)*32 + 4*ebp + 2 + (ej&1)] = hB;                             \
    }                                                                         \
    __syncthreads();                        /* staging + G-reads done */      \
    if (tid == 0) {                                                           \
        asm volatile("fence.proxy.async.shared::cta;" ::: "memory");          \
        unsigned src  = sbase + (OFF_ST + Lc*256)*4u;                         \
        unsigned dstb = abase + (((Lc << 11) + (rank << 8)) << 2);            \
        _Pragma("unroll")                                                     \
        for (int r = 0; r < 8; r++) blkcp(mapa_(dstb, r), src, mapa_(fL, r)); \
    }                                                                         \
} while (0)

    for (int t = 0; t < 1056; t++) {
        const unsigned pc = t & 1, pp = (t - 1) & 1;
        if (t < 1024 && tid < 16) A2[6144 + 2*tid] = xn;
        __syncthreads();
        if (tid < 16 && t + 1 < 1024) xn = xg[(b0 + tid)*1024 + t + 1];
        if (t >= 1024) { waitp(fx, phx); phx ^= 1; }
        if (tid == 0 && t >= 1023 && t < 1055) exptx(fx, 64);

        LAYER(0, e1, f1, WO1, );
        LAYER(1, e2, f2, WO2,
              waitp(f1, pc);
              seg(Wd + 8320, A2, 64, kh, l2, bq8, a0, a1, a2, a3); );
        LAYER(2, e3, f3, WO3,
              waitp(f1, pc);
              seg(Wd + 8320, A2, 64, kh, l2, bq8, a0, a1, a2, a3);
              waitp(f2, pc);
              seg(Wd + 16512, A2 + 2048, 64, kh, l2, bq8, a0, a1, a2, a3); );

        // head (needs h3(t) locally)
        float o = 0.f;
        const int hb = 2*rank + (tid >> 5);
        if (tid < 64) {
            waitp(f3, pc);
            float s = 0.f;
            for (int g = lane; g < 385; g += 32)
                s += A2[((g >> 1) << 5) + 2*hb + (g & 1)] * WL[g];
            #pragma unroll
            for (int off = 16; off; off >>= 1) s += __shfl_xor_sync(0xffffffffu, s, off);
            if (lane == 0) {
                o = s + WL[385];
                out[(b0 + hb)*1056 + t] = o;
            }
        }
        __syncthreads();                       // all x(t)/A2 reads done
        if (tid < 8) rarr(ex, tid);
        if (t >= 1023 && t < 1055 && tid < 64 && lane == 0) {
            waitp(ex, pc);                     // x slot free everywhere
            const unsigned ox = (unsigned)(6144 + 2*hb) << 2;
            #pragma unroll
            for (int r = 0; r < 8; r++) sta(rb[r] + ox, mapa_(fx, r), o);
        }
        __syncthreads();
    }

    if (tid == 0) { waitp(f1, 1); waitp(f2, 1); waitp(f3, 1); }
    __syncthreads();
    asm volatile("barrier.cluster.arrive.aligned;" ::: "memory");
    asm volatile("barrier.cluster.wait.aligned;" ::: "memory");
}

extern "C" void kernel_launch(void* const* d_in, const int* in_sizes, int n_in,
                              void* d_out, int out_size) {
    cudaFuncSetAttribute(lstm_k, cudaFuncAttributeMaxDynamicSharedMemorySize, SMEM_BYTES);
    lstm_k<<<128, 512, SMEM_BYTES>>>(
        (const float*)d_in[0],
        (const float*)d_in[1], (const float*)d_in[2],
        (const float*)d_in[3], (const float*)d_in[4],
        (const float*)d_in[5], (const float*)d_in[6],
        (const float*)d_in[7], (const float*)d_in[8],
        (const float*)d_in[9], (const float*)d_in[10],
        (const float*)d_in[11], (const float*)d_in[12],
        (const float*)d_in[13], (const float*)d_in[14],
        (float*)d_out);
}

// round 12
// speedup vs baseline: 1.4159x; 1.0134x over previous
#include <cuda_runtime.h>
typedef unsigned long long ull;

#define WO1 0
#define WO2 (65*128)
#define WO3 (194*128)
#define WTOT (387*128)            // 49536 floats
#define OFF_A  WTOT               // A2: 193 kp * 32 = 6176
#define OFF_G  (OFF_A + 6176)     // 64*16
#define OFF_WL (OFF_G + 1024)     // 386
#define OFF_MB (OFF_WL + 386)     // byte 228488 (8B aligned)
#define OFF_ST (OFF_MB + 18)      // byte 228560 (16B aligned)
#define SMEM_FLOATS (OFF_ST + 768)
#define SMEM_BYTES (SMEM_FLOATS*4)   // 231632 B

__device__ __forceinline__ void fma2(ull& a, ull b, ull c) {
    asm("fma.rn.f32x2 %0, %1, %2, %0;" : "+l"(a) : "l"(b), "l"(c));
}
__device__ __forceinline__ float hadd(ull v) {
    float lo, hi; asm("mov.b64 {%0,%1}, %2;" : "=f"(lo), "=f"(hi) : "l"(v));
    return lo + hi;
}
__device__ __forceinline__ float tha(float x) {
    float y; asm("tanh.approx.f32 %0, %1;" : "=f"(y) : "f"(x)); return y;
}
__device__ __forceinline__ unsigned mapa_(unsigned a, int r) {
    unsigned ra; asm("mapa.shared::cluster.u32 %0, %1, %2;" : "=r"(ra) : "r"(a), "r"(r));
    return ra;
}
__device__ __forceinline__ void mbinit(unsigned a, unsigned n) {
    asm volatile("mbarrier.init.shared.b64 [%0], %1;" :: "r"(a), "r"(n) : "memory");
}
__device__ __forceinline__ void exptx(unsigned a, unsigned n) {
    asm volatile("mbarrier.arrive.expect_tx.shared.b64 _, [%0], %1;" :: "r"(a), "r"(n) : "memory");
}
__device__ __forceinline__ void rarr(unsigned a, int r) {
    unsigned ra = mapa_(a, r);
    asm volatile("mbarrier.arrive.release.cluster.shared::cluster.b64 _, [%0];" :: "r"(ra) : "memory");
}
__device__ __forceinline__ void sta(unsigned d, unsigned m, float v) {
    asm volatile("st.async.shared::cluster.mbarrier::complete_tx::bytes.b32 [%0], %1, [%2];"
                 :: "r"(d), "r"(__float_as_uint(v)), "r"(m) : "memory");
}
__device__ __forceinline__ void blkcp(unsigned dst, unsigned src, unsigned mb) {
    asm volatile("cp.async.bulk.shared::cluster.shared::cta.mbarrier::complete_tx::bytes [%0], [%1], %2, [%3];"
                 :: "r"(dst), "r"(src), "r"(1024u), "r"(mb) : "memory");
}
__device__ __forceinline__ void waitp(unsigned a, unsigned p) {
    unsigned d;
    asm volatile("{\n.reg .pred P;\nmbarrier.try_wait.parity.acquire.cluster.shared::cta.b64 P,[%1],%2;\nselp.b32 %0,1,0,P;\n}"
                 : "=r"(d) : "r"(a), "r"(p) : "memory");
    while (!d)
        asm volatile("{\n.reg .pred P;\nmbarrier.try_wait.parity.acquire.cluster.shared::cta.b64 P,[%1],%2,0x989680;\nselp.b32 %0,1,0,P;\n}"
                     : "=r"(d) : "r"(a), "r"(p) : "memory");
}
// 16 kp of one segment quarter: weight 1 wf, acts 4 wf, 8 FMA2/lane
__device__ __forceinline__ void segc16(const ull* __restrict__ Wu, const ull* __restrict__ Au,
                                       int kp0, int wrow, int acol, ull* acc) {
    #pragma unroll 8
    for (int i = 0; i < 16; i++) {
        const int kp = kp0 + i;
        const ull w2 = Wu[(kp << 6) + wrow];
        const ull* ap = Au + (kp << 4) + acol;
        ulonglong2 q0 = *(const ulonglong2*)(ap);
        ulonglong2 q1 = *(const ulonglong2*)(ap + 2);
        ulonglong2 q2 = *(const ulonglong2*)(ap + 4);
        ulonglong2 q3 = *(const ulonglong2*)(ap + 6);
        fma2(acc[0], w2, q0.x); fma2(acc[1], w2, q0.y);
        fma2(acc[2], w2, q1.x); fma2(acc[3], w2, q1.y);
        fma2(acc[4], w2, q2.x); fma2(acc[5], w2, q2.y);
        fma2(acc[6], w2, q3.x); fma2(acc[7], w2, q3.y);
    }
}

__global__ void __launch_bounds__(512, 1) __cluster_dims__(8, 1, 1)
lstm_k(const float* __restrict__ xg,
       const float* __restrict__ Wih1, const float* __restrict__ Whh1,
       const float* __restrict__ bih1, const float* __restrict__ bhh1,
       const float* __restrict__ Wih2, const float* __restrict__ Whh2,
       const float* __restrict__ bih2, const float* __restrict__ bhh2,
       const float* __restrict__ Wih3, const float* __restrict__ Whh3,
       const float* __restrict__ bih3, const float* __restrict__ bhh3,
       const float* __restrict__ Wlin, const float* __restrict__ blin,
       float* __restrict__ out)
{
    extern __shared__ float sm[];
    float* W  = sm;
    float* A2 = sm + OFF_A;
    float* G  = sm + OFF_G;
    float* WL = sm + OFF_WL;
    float* ST = sm + OFF_ST;

    const int tid = threadIdx.x;
    unsigned ur; asm("mov.u32 %0, %%cluster_ctarank;" : "=r"(ur));
    const int rank = (int)ur;
    const int b0 = (blockIdx.x >> 3) * 16;

    const unsigned sbase = (unsigned)__cvta_generic_to_shared(sm);
    const unsigned e1 = sbase + (OFF_MB + 0)*4,  e2 = sbase + (OFF_MB + 2)*4;
    const unsigned e3 = sbase + (OFF_MB + 4)*4;
    const unsigned f1 = sbase + (OFF_MB + 6)*4,  f2 = sbase + (OFF_MB + 8)*4;
    const unsigned f3 = sbase + (OFF_MB + 10)*4;
    const unsigned fx = sbase + (OFF_MB + 12)*4, ex = sbase + (OFF_MB + 14)*4;

    // ---- one-time load: W interleaved k-pairs, col order [h_L rec | x,pad | h1 | h2] ----
    {
        const float* WihA[3] = {Wih1, Wih2, Wih3};
        const float* WhhA[3] = {Whh1, Whh2, Whh3};
        const int KihA[3] = {1, 129, 257};
        const int KPA[3]  = {65, 129, 193};
        const int WOA[3]  = {WO1, WO2, WO3};
        for (int L = 0; L < 3; L++) {
            const int Kih = KihA[L], KP = KPA[L];
            float* Wd = W + WOA[L];
            for (int i = tid; i < KP*128; i += 512) {
                int wkp = i >> 7, r = i & 127, l = r >> 1, par = r & 1;
                int grow = ((l >> 4) << 7) + (rank << 4) + (l & 15);
                float v;
                if (wkp < 64)        v = WhhA[L][grow*128 + 2*wkp + par];
                else if (wkp == 64)  v = par ? 0.0f : WihA[L][grow*Kih];
                else                 v = WihA[L][grow*Kih + 1 + 2*(wkp - 65) + par];
                if ((l >> 4) != 2) v *= 0.5f;   // i,f,o pre-scaled for tanh-sigmoid
                Wd[i] = v;
            }
        }
        for (int i = tid; i < 384; i += 512) WL[i] = Wlin[i + 1];
        if (tid == 0) { WL[384] = Wlin[0]; WL[385] = blin[0]; }
        for (int i = tid; i < 6176; i += 512) A2[i] = 0.0f;
        if (tid == 0) {
            mbinit(e1, 8); mbinit(e2, 8); mbinit(e3, 8); mbinit(ex, 8);
            mbinit(f1, 1); mbinit(f2, 1); mbinit(f3, 1); mbinit(fx, 1);
        }
    }
    // per-thread epilogue biases in registers (pre-scaled)
    float bR[3][4];
    {
        const float* bihA[3] = {bih1, bih2, bih3};
        const float* bhhA[3] = {bhh1, bhh2, bhh3};
        #pragma unroll
        for (int L = 0; L < 3; L++)
            #pragma unroll
            for (int g = 0; g < 4; g++) {
                int grow = (g << 7) + (rank << 4) + ((tid >> 3) & 15);
                float b = bihA[L][grow] + bhhA[L][grow];
                bR[L][g] = (g == 2) ? b : 0.5f * b;
            }
    }
    __syncthreads();
    asm volatile("barrier.cluster.arrive.aligned;" ::: "memory");
    asm volatile("barrier.cluster.wait.aligned;" ::: "memory");

    const unsigned abase = sbase + OFF_A*4;
    unsigned rb[8];
    #pragma unroll
    for (int r = 0; r < 8; r++) rb[r] = mapa_(abase, r);

    const ull* Wul = (const ull*)W;
    const ull* A2u = (const ull*)A2;
    const int warpid = tid >> 5, lane = tid & 31;
    const int kq   = warpid >> 2;                         // k-quarter
    const int wrow = ((warpid & 3) << 4) + (lane & 15);   // gate row 0..63
    const int acol = (lane >> 4) << 3;                    // batch half: ull 0 / 8
    const int kp0  = kq << 4;
    const int ej = tid >> 3, ebp = tid & 7;
    float* Gp = G + wrow*16 + acol;
    float cst[3][2] = {{0.f,0.f},{0.f,0.f},{0.f,0.f}};
    float xn = (tid < 16) ? xg[(b0 + tid) * 1024] : 0.0f;
    unsigned phx = 0;

#define LAYER(Lc, eL, fL, WUOFF, PRE) do {                                    \
    const ull* Wu = Wul + WUOFF;                                              \
    if (t) waitp(fL, pp);                   /* recurrent h_L(t-1) arrived */  \
    if (tid == 0) exptx(fL, 8192);          /* fresh phase */                 \
    ull acc[8] = {0,0,0,0,0,0,0,0};                                           \
    segc16(Wu, A2u + (Lc << 10), kp0, wrow, acol, acc);   /* rec h_L */       \
    if (kq == 0) {                                        /* x (1 kp) */      \
        const ull w2 = Wu[4096 + wrow];                                       \
        const ull* ap = A2u + 3072 + acol;                                    \
        ulonglong2 q0 = *(const ulonglong2*)(ap);                             \
        ulonglong2 q1 = *(const ulonglong2*)(ap + 2);                         \
        ulonglong2 q2 = *(const ulonglong2*)(ap + 4);                         \
        ulonglong2 q3 = *(const ulonglong2*)(ap + 6);                         \
        fma2(acc[0], w2, q0.x); fma2(acc[1], w2, q0.y);                       \
        fma2(acc[2], w2, q1.x); fma2(acc[3], w2, q1.y);                       \
        fma2(acc[4], w2, q2.x); fma2(acc[5], w2, q2.y);                       \
        fma2(acc[6], w2, q3.x); fma2(acc[7], w2, q3.y);                       \
    }                                                                         \
    __syncthreads();                        /* early reads done CTA-wide */   \
    if (tid < 8) rarr(eL, tid);                                               \
    PRE                                                                       \
    float p0 = hadd(acc[0]), p1 = hadd(acc[1]), p2 = hadd(acc[2]);            \
    float p3 = hadd(acc[3]), p4 = hadd(acc[4]), p5 = hadd(acc[5]);            \
    float p6 = hadd(acc[6]), p7 = hadd(acc[7]);                               \
    if (kq == 0) {                                                            \
        *(float4*)Gp = make_float4(p0, p1, p2, p3);                           \
        *(float4*)(Gp + 4) = make_float4(p4, p5, p6, p7);                     \
    }                                                                         \
    __syncthreads();                                                          \
    if (kq == 1) {                                                            \
        float4 v0 = *(float4*)Gp, v1 = *(float4*)(Gp + 4);                    \
        v0.x += p0; v0.y += p1; v0.z += p2; v0.w += p3;                       \
        v1.x += p4; v1.y += p5; v1.z += p6; v1.w += p7;                       \
        *(float4*)Gp = v0; *(float4*)(Gp + 4) = v1;                           \
    }                                                                         \
    __syncthreads();                                                          \
    if (kq == 2) {                                                            \
        float4 v0 = *(float4*)Gp, v1 = *(float4*)(Gp + 4);                    \
        v0.x += p0; v0.y += p1; v0.z += p2; v0.w += p3;                       \
        v1.x += p4; v1.y += p5; v1.z += p6; v1.w += p7;                       \
        *(float4*)Gp = v0; *(float4*)(Gp + 4) = v1;                           \
    }                                                                         \
    __syncthreads();                                                          \
    if (kq == 3) {                                                            \
        float4 v0 = *(float4*)Gp, v1 = *(float4*)(Gp + 4);                    \
        v0.x += p0; v0.y += p1; v0.z += p2; v0.w += p3;                       \
        v1.x += p4; v1.y += p5; v1.z += p6; v1.w += p7;                       \
        *(float4*)Gp = v0; *(float4*)(Gp + 4) = v1;                           \
    }                                                                         \
    __syncthreads();                        /* G complete + visible */        \
    if (tid < 128) {                        /* epilogue: 2 cells/thread */    \
        const int ba = 2*ebp;                                                 \
        const float bi = bR[Lc][0], bf = bR[Lc][1];                           \
        const float bg = bR[Lc][2], bo = bR[Lc][3];                           \
        float ii = fmaf(0.5f, tha(G[ej*16 + ba] + bi), 0.5f);                 \
        float ff = fmaf(0.5f, tha(G[(16+ej)*16 + ba] + bf), 0.5f);            \
        float gg = tha(G[(32+ej)*16 + ba] + bg);                              \
        float oo = fmaf(0.5f, tha(G[(48+ej)*16 + ba] + bo), 0.5f);            \
        float c = ff*cst[Lc][0] + ii*gg; cst[Lc][0] = c; float hA = oo*tha(c);\
        ii = fmaf(0.5f, tha(G[ej*16 + ba+1] + bi), 0.5f);                     \
        ff = fmaf(0.5f, tha(G[(16+ej)*16 + ba+1] + bf), 0.5f);                \
        gg = tha(G[(32+ej)*16 + ba+1] + bg);                                  \
        oo = fmaf(0.5f, tha(G[(48+ej)*16 + ba+1] + bo), 0.5f);                \
        c = ff*cst[Lc][1] + ii*gg; cst[Lc][1] = c; float hB = oo*tha(c);      \
        waitp(eL, pc);                      /* prev staging fully read */     \
        float* SL = ST + Lc*256;                                              \
        SL[(ej>>1)*32 + 4*ebp + (ej&1)] = hA;                                 \
        SL[(ej>>1)*32 + 4*ebp + 2 + (ej&1)] = hB;                             \
    }                                                                         \
    __syncthreads();                        /* staging + G-reads done */      \
    if (tid == 0) {                                                           \
        asm volatile("fence.proxy.async.shared::cta;" ::: "memory");          \
        unsigned src  = sbase + (OFF_ST + Lc*256)*4u;                         \
        unsigned dstb = abase + (((Lc << 11) + (rank << 8)) << 2);            \
        _Pragma("unroll")                                                     \
        for (int r = 0; r < 8; r++) blkcp(mapa_(dstb, r), src, mapa_(fL, r)); \
    }                                                                         \
} while (0)

    for (int t = 0; t < 1056; t++) {
        const unsigned pc = t & 1, pp = (t - 1) & 1;
        if (t < 1024 && tid < 16) A2[6144 + 2*tid] = xn;
        __syncthreads();
        if (tid < 16 && t + 1 < 1024) xn = xg[(b0 + tid)*1024 + t + 1];
        if (t >= 1024) { waitp(fx, phx); phx ^= 1; }
        if (tid == 0 && t >= 1023 && t < 1055) exptx(fx, 64);

        LAYER(0, e1, f1, 0, );
        LAYER(1, e2, f2, 4160,
              waitp(f1, pc);
              segc16(Wu + 4160, A2u, kp0, wrow, acol, acc); );
        LAYER(2, e3, f3, 12416,
              waitp(f1, pc);
              segc16(Wu + 4160, A2u, kp0, wrow, acol, acc);
              waitp(f2, pc);
              segc16(Wu + 8256, A2u + 1024, kp0, wrow, acol, acc); );

        // head (needs h3(t) locally)
        float o = 0.f;
        const int hb = 2*rank + (tid >> 5);
        if (tid < 64) {
            waitp(f3, pc);
            float s = 0.f;
            for (int g = lane; g < 385; g += 32)
                s += A2[((g >> 1) << 5) + 2*hb + (g & 1)] * WL[g];
            #pragma unroll
            for (int off = 16; off; off >>= 1) s += __shfl_xor_sync(0xffffffffu, s, off);
            if (lane == 0) {
                o = s + WL[385];
                out[(b0 + hb)*1056 + t] = o;
            }
        }
        __syncthreads();                       // all x(t)/A2 reads done
        if (tid < 8) rarr(ex, tid);
        if (t >= 1023 && t < 1055 && tid < 64 && lane == 0) {
            waitp(ex, pc);                     // x slot free everywhere
            const unsigned ox = (unsigned)(6144 + 2*hb) << 2;
            #pragma unroll
            for (int r = 0; r < 8; r++) sta(rb[r] + ox, mapa_(fx, r), o);
        }
        __syncthreads();
    }

    if (tid == 0) { waitp(f1, 1); waitp(f2, 1); waitp(f3, 1); }
    __syncthreads();
    asm volatile("barrier.cluster.arrive.aligned;" ::: "memory");
    asm volatile("barrier.cluster.wait.aligned;" ::: "memory");
}

extern "C" void kernel_launch(void* const* d_in, const int* in_sizes, int n_in,
                              void* d_out, int out_size) {
    cudaFuncSetAttribute(lstm_k, cudaFuncAttributeMaxDynamicSharedMemorySize, SMEM_BYTES);
    lstm_k<<<128, 512, SMEM_BYTES>>>(
        (const float*)d_in[0],
        (const float*)d_in[1], (const float*)d_in[2],
        (const float*)d_in[3], (const float*)d_in[4],
        (const float*)d_in[5], (const float*)d_in[6],
        (const float*)d_in[7], (const float*)d_in[8],
        (const float*)d_in[9], (const float*)d_in[10],
        (const float*)d_in[11], (const float*)d_in[12],
        (const float*)d_in[13], (const float*)d_in[14],
        (float*)d_out);
}